// round 1
// baseline (speedup 1.0000x reference)
#include <cuda_runtime.h>

// DigitCaps dynamic routing, fully fused.
// B=64, R=6912, I=8, C=10, O=16, 3 routing iterations.
//
// Pass structure (all on default stream, graph-capturable):
//   zero_acc
//   transpose x[B,R,I] -> xT[R,B,I]            (coalesced per-r access later)
//   pass<0>:  p = W^T x per (c,b,r); acc += p              (uniform probs)
//   squash<0>: out0 = squash(acc / R); zero acc
//   pass<1>:  p; d = p.out0; logits = d; w = exp(d); acc_w += w; acc_p += w*p
//   squash<1>: out1 = squash(acc_p/acc_w); zero acc
//   pass<2>:  p; d = p.out1; lg = logits + d; w = exp(lg); accumulate
//   squash<2>: out2 -> d_out
//
// exp without max-subtraction is safe: |logits| <~ 32 (|delta| <= ||p_row||*||out||,
// ||out||<1, p entries ~N(0,8)); fp32 range 1e38 >> worst accumulant ~1e17.

#define R_DIM 6912
#define B_DIM 64
#define C_DIM 10

typedef unsigned long long u64;

__device__ __align__(16) float g_xT[R_DIM * B_DIM * 8];        // 14.2 MB
__device__ __align__(16) float g_logits[C_DIM * R_DIM * B_DIM]; // 17.7 MB
__device__ __align__(16) float g_acc[C_DIM * B_DIM * 17];       // [c][b][0..15]=sum w*p, [16]=sum w
__device__ __align__(16) float g_out[C_DIM * B_DIM * 16];       // per-iteration squash output

// ---- packed f32x2 helpers (FFMA2 only reachable via PTX) ----
__device__ __forceinline__ u64 pack2(float lo, float hi) {
    u64 r; asm("mov.b64 %0, {%1, %2};" : "=l"(r) : "f"(lo), "f"(hi)); return r;
}
__device__ __forceinline__ void unpack2(u64 v, float& lo, float& hi) {
    asm("mov.b64 {%0, %1}, %2;" : "=f"(lo), "=f"(hi) : "l"(v));
}
__device__ __forceinline__ u64 fma2(u64 a, u64 b, u64 c) {
    u64 d; asm("fma.rn.f32x2 %0, %1, %2, %3;" : "=l"(d) : "l"(a), "l"(b), "l"(c)); return d;
}
__device__ __forceinline__ u64 add2(u64 a, u64 b) {
    u64 d; asm("add.rn.f32x2 %0, %1, %2;" : "=l"(d) : "l"(a), "l"(b)); return d;
}

__global__ void k_zero_acc() {
    for (int i = threadIdx.x; i < C_DIM * B_DIM * 17; i += blockDim.x) g_acc[i] = 0.0f;
}

// x[b][r][i] -> xT[r][b][i], float4-granular
__global__ void k_transpose(const float* __restrict__ x) {
    int j = blockIdx.x * blockDim.x + threadIdx.x;       // float4 index, total R*B*2
    if (j < R_DIM * B_DIM * 2) {
        int b   = j / (R_DIM * 2);
        int rem = j - b * (R_DIM * 2);
        int r   = rem >> 1;
        int h   = rem & 1;
        float4 v = reinterpret_cast<const float4*>(x)[j];
        reinterpret_cast<float4*>(g_xT)[(r * B_DIM + b) * 2 + h] = v;
    }
}

// MODE 0: uniform accumulation (iteration 0)
// MODE 1: delta from out_prev, store logits, exp-weighted accumulation
// MODE 2: delta from out_prev, add to stored logits, exp-weighted accumulation
template <int MODE>
__global__ void __launch_bounds__(128)
k_pass(const float* __restrict__ Wg) {
    const int c    = blockIdx.y;
    const int warp = threadIdx.x >> 5;
    const int lane = threadIdx.x & 31;
    const int b0   = lane * 2;                 // this lane owns b0, b0+1, all 16 o

    __shared__ float sacc[4 * B_DIM * 17];     // per-warp partial accumulators

    // out_prev for this lane's two b's, packed as o-pairs (constant over r loop)
    u64 outp0[8], outp1[8];
    if (MODE != 0) {
        const u64* ob = reinterpret_cast<const u64*>(g_out + (c * B_DIM + b0) * 16);
        #pragma unroll
        for (int k = 0; k < 8; k++) { outp0[k] = ob[k]; outp1[k] = ob[8 + k]; }
    }

    u64 accp0[8], accp1[8];
    #pragma unroll
    for (int k = 0; k < 8; k++) { accp0[k] = 0ull; accp1[k] = 0ull; }
    float accw0 = 0.0f, accw1 = 0.0f;

    const int r0 = blockIdx.x * 64 + warp;     // this warp: r0, r0+4, ..., r0+60

    #pragma unroll 1
    for (int k = 0; k < 16; k++) {
        const int r = r0 + k * 4;

        // x for b0,b0+1 at row r (coalesced: lane stride 64B)
        const float4* xp = reinterpret_cast<const float4*>(g_xT + (size_t)r * (B_DIM * 8) + b0 * 8);
        float4 xa = xp[0], xb = xp[1], xc = xp[2], xd = xp[3];
        float xf0[8] = {xa.x, xa.y, xa.z, xa.w, xb.x, xb.y, xb.z, xb.w};
        float xf1[8] = {xc.x, xc.y, xc.z, xc.w, xd.x, xd.y, xd.z, xd.w};

        // W[c][r] : 8 x 16 contiguous floats (uniform address across warp -> broadcast)
        const ulonglong2* Wp =
            reinterpret_cast<const ulonglong2*>(Wg + ((size_t)c * R_DIM + r) * 128);

        u64 p0[8], p1[8];
        #pragma unroll
        for (int t = 0; t < 8; t++) { p0[t] = 0ull; p1[t] = 0ull; }

        #pragma unroll
        for (int i = 0; i < 8; i++) {
            ulonglong2 q0 = Wp[i * 4 + 0];
            ulonglong2 q1 = Wp[i * 4 + 1];
            ulonglong2 q2 = Wp[i * 4 + 2];
            ulonglong2 q3 = Wp[i * 4 + 3];
            u64 x0 = pack2(xf0[i], xf0[i]);
            u64 x1 = pack2(xf1[i], xf1[i]);
            p0[0] = fma2(q0.x, x0, p0[0]); p0[1] = fma2(q0.y, x0, p0[1]);
            p0[2] = fma2(q1.x, x0, p0[2]); p0[3] = fma2(q1.y, x0, p0[3]);
            p0[4] = fma2(q2.x, x0, p0[4]); p0[5] = fma2(q2.y, x0, p0[5]);
            p0[6] = fma2(q3.x, x0, p0[6]); p0[7] = fma2(q3.y, x0, p0[7]);
            p1[0] = fma2(q0.x, x1, p1[0]); p1[1] = fma2(q0.y, x1, p1[1]);
            p1[2] = fma2(q1.x, x1, p1[2]); p1[3] = fma2(q1.y, x1, p1[3]);
            p1[4] = fma2(q2.x, x1, p1[4]); p1[5] = fma2(q2.y, x1, p1[5]);
            p1[6] = fma2(q3.x, x1, p1[6]); p1[7] = fma2(q3.y, x1, p1[7]);
        }

        if (MODE == 0) {
            #pragma unroll
            for (int t = 0; t < 8; t++) {
                accp0[t] = add2(accp0[t], p0[t]);
                accp1[t] = add2(accp1[t], p1[t]);
            }
        } else {
            // delta = p . out_prev (per b, in-lane dot over 16 o)
            u64 d0 = 0ull, d1 = 0ull;
            #pragma unroll
            for (int t = 0; t < 8; t++) {
                d0 = fma2(p0[t], outp0[t], d0);
                d1 = fma2(p1[t], outp1[t], d1);
            }
            float lo, hi;
            unpack2(d0, lo, hi); float del0 = lo + hi;
            unpack2(d1, lo, hi); float del1 = lo + hi;

            float* lg = g_logits + ((size_t)c * R_DIM + r) * B_DIM + b0;
            if (MODE == 2) {
                float2 old = *reinterpret_cast<const float2*>(lg);
                del0 += old.x; del1 += old.y;
            }
            if (MODE == 1) {
                *reinterpret_cast<float2*>(lg) = make_float2(del0, del1);
            }
            // overflow guard (never triggers statistically; softmax is shift/clamp-safe here)
            del0 = fminf(del0, 70.0f); del1 = fminf(del1, 70.0f);
            float w0 = __expf(del0), w1 = __expf(del1);
            accw0 += w0; accw1 += w1;
            u64 wd0 = pack2(w0, w0), wd1 = pack2(w1, w1);
            #pragma unroll
            for (int t = 0; t < 8; t++) {
                accp0[t] = fma2(p0[t], wd0, accp0[t]);
                accp1[t] = fma2(p1[t], wd1, accp1[t]);
            }
        }
    }

    // per-warp partials -> smem (disjoint slots, no atomics)
    float* s0 = sacc + (warp * B_DIM + b0) * 17;
    #pragma unroll
    for (int t = 0; t < 8; t++) {
        float lo, hi;
        unpack2(accp0[t], lo, hi); s0[2 * t] = lo; s0[2 * t + 1] = hi;
        unpack2(accp1[t], lo, hi); s0[17 + 2 * t] = lo; s0[17 + 2 * t + 1] = hi;
    }
    s0[16] = accw0; s0[17 + 16] = accw1;
    __syncthreads();

    // fold 4 warps, one global atomic per (b,o) per CTA
    for (int idx = threadIdx.x; idx < B_DIM * 17; idx += 128) {
        float v = sacc[idx] + sacc[1088 + idx] + sacc[2 * 1088 + idx] + sacc[3 * 1088 + idx];
        atomicAdd(&g_acc[c * (B_DIM * 17) + idx], v);
    }
}

template <int MODE, bool FINAL>
__global__ void k_squash(float* __restrict__ dout) {
    int c = blockIdx.x, b = threadIdx.x;   // 10 blocks x 64 threads
    float* a = g_acc + c * (B_DIM * 17) + b * 17;
    float invw = (MODE == 0) ? (1.0f / (float)R_DIM) : (1.0f / a[16]);
    float s[16], sq = 0.0f;
    #pragma unroll
    for (int o = 0; o < 16; o++) { s[o] = a[o] * invw; sq += s[o] * s[o]; }
    float coef = sq / ((1.0f + sq) * sqrtf(sq));
    float* dst = FINAL ? (dout + (c * B_DIM + b) * 16) : (g_out + (c * B_DIM + b) * 16);
    #pragma unroll
    for (int o = 0; o < 16; o++) dst[o] = coef * s[o];
    if (!FINAL) {
        #pragma unroll
        for (int t = 0; t < 17; t++) a[t] = 0.0f;   // ready for next pass
    }
}

extern "C" void kernel_launch(void* const* d_in, const int* in_sizes, int n_in,
                              void* d_out, int out_size) {
    const float* x = (const float*)d_in[0];          // [64, 6912, 8]
    const float* W = (const float*)d_in[1];          // [10, 6912, 8, 16]
    float* out = (float*)d_out;                      // [10, 64, 1, 1, 16]

    k_zero_acc<<<1, 256>>>();
    k_transpose<<<(R_DIM * B_DIM * 2 + 255) / 256, 256>>>(x);

    dim3 grid(R_DIM / 64, C_DIM);                    // (108, 10)
    k_pass<0><<<grid, 128>>>(W);
    k_squash<0, false><<<C_DIM, B_DIM>>>(nullptr);
    k_pass<1><<<grid, 128>>>(W);
    k_squash<1, false><<<C_DIM, B_DIM>>>(nullptr);
    k_pass<2><<<grid, 128>>>(W);
    k_squash<2, true><<<C_DIM, B_DIM>>>(out);
}